// round 2
// baseline (speedup 1.0000x reference)
#include <cuda_runtime.h>
#include <cstdint>

// Shapes (fixed by the problem)
#define Bb   8
#define LQ   2048
#define LKt  2048
#define Dd   128
#define Hh   8

// Scratch: head-major Q/K/V [b][h][l][d] and attention output [b][l][h*128]
__device__ float g_Q[(size_t)Bb * Hh * LQ * Dd];
__device__ float g_K[(size_t)Bb * Hh * LKt * Dd];
__device__ float g_V[(size_t)Bb * Hh * LKt * Dd];
__device__ float g_AT[(size_t)Bb * LQ * Hh * Dd];

// ---------------------------------------------------------------------------
// Generic 128x128-tile SGEMM. C = A[M x KTOT] * W[KTOT x N(=gridDim.y*128)] + bias
// SCATTER=true: write head-major (QKV proj). SCATTER=false: plain row-major (stride NW).
// ---------------------------------------------------------------------------
template <int KTOT, int NW, bool SCATTER>
__global__ __launch_bounds__(256) void gemm_kernel(const float* __restrict__ A,
                                                   const float* __restrict__ Bw,
                                                   const float* __restrict__ bias,
                                                   float* __restrict__ C)
{
    __shared__ float As[16 * 128];   // k-major, XOR swizzled
    __shared__ float Bs[16 * 128];   // k-major, XOR swizzled

    const int tid = threadIdx.x;
    const int tx = tid & 15, ty = tid >> 4;
    const int m0 = blockIdx.x * 128;
    const int n0 = blockIdx.y * 128;

    float acc[8][8];
#pragma unroll
    for (int i = 0; i < 8; ++i)
#pragma unroll
        for (int j = 0; j < 8; ++j) acc[i][j] = 0.f;

    for (int kc = 0; kc < KTOT; kc += 16) {
        __syncthreads();
        // Load A tile: 128 rows x 16 k, transpose into k-major with swizzle
#pragma unroll
        for (int it = 0; it < 2; ++it) {
            int f4 = tid + it * 256;          // 0..511
            int r  = f4 >> 2;                 // 0..127
            int kg = (f4 & 3) << 2;           // 0,4,8,12
            float4 av = *(const float4*)&A[(size_t)(m0 + r) * KTOT + kc + kg];
            float avv[4] = {av.x, av.y, av.z, av.w};
#pragma unroll
            for (int jj = 0; jj < 4; ++jj) {
                int k = kg + jj;
                As[k * 128 + ((((r >> 2) ^ k) & 31) << 2) + (r & 3)] = avv[jj];
            }
        }
        // Load B tile: 16 k x 128 n
#pragma unroll
        for (int it = 0; it < 2; ++it) {
            int f4 = tid + it * 256;
            int k  = f4 >> 5;                 // 0..15
            int n4 = f4 & 31;
            float4 bv = *(const float4*)&Bw[(size_t)(kc + k) * NW + n0 + (n4 << 2)];
            *(float4*)&Bs[k * 128 + (((n4 ^ k) & 31) << 2)] = bv;
        }
        __syncthreads();

#pragma unroll
        for (int kk = 0; kk < 16; ++kk) {
            float4 a0 = *(const float4*)&As[kk * 128 + ((((2 * ty) ^ kk) & 31) << 2)];
            float4 a1 = *(const float4*)&As[kk * 128 + ((((2 * ty + 1) ^ kk) & 31) << 2)];
            float4 b0 = *(const float4*)&Bs[kk * 128 + ((((2 * tx) ^ kk) & 31) << 2)];
            float4 b1 = *(const float4*)&Bs[kk * 128 + ((((2 * tx + 1) ^ kk) & 31) << 2)];
            float a[8] = {a0.x, a0.y, a0.z, a0.w, a1.x, a1.y, a1.z, a1.w};
            float b[8] = {b0.x, b0.y, b0.z, b0.w, b1.x, b1.y, b1.z, b1.w};
#pragma unroll
            for (int i = 0; i < 8; ++i)
#pragma unroll
                for (int j = 0; j < 8; ++j) acc[i][j] += a[i] * b[j];
        }
    }

    // Epilogue
#pragma unroll
    for (int i = 0; i < 8; ++i) {
        int m = m0 + 8 * ty + i;
        int nb = n0 + 8 * tx;
        float4 o0, o1;
        o0.x = acc[i][0] + bias[nb + 0];
        o0.y = acc[i][1] + bias[nb + 1];
        o0.z = acc[i][2] + bias[nb + 2];
        o0.w = acc[i][3] + bias[nb + 3];
        o1.x = acc[i][4] + bias[nb + 4];
        o1.y = acc[i][5] + bias[nb + 5];
        o1.z = acc[i][6] + bias[nb + 6];
        o1.w = acc[i][7] + bias[nb + 7];
        if (SCATTER) {
            // block's n-range is exactly one head (128 cols): h = blockIdx.y, d = 8tx+j
            int bidx = m >> 11, l = m & 2047;
            size_t base = (((size_t)bidx * Hh + blockIdx.y) * LQ + l) * Dd + 8 * tx;
            *(float4*)&C[base]     = o0;
            *(float4*)&C[base + 4] = o1;
        } else {
            size_t base = (size_t)m * NW + n0 + 8 * tx;
            *(float4*)&C[base]     = o0;
            *(float4*)&C[base + 4] = o1;
        }
    }
}

// ---------------------------------------------------------------------------
// Flash attention, fp32. One CTA = one (b,h) x 64 q-rows. K-tiles of 128.
// smem: Qt[128k][64r], Kt[128k][128c], Vs[128j][128c], Ps[64r][128c], stats.
// All tiles XOR-swizzled for (near) conflict-free float4 access.
// ---------------------------------------------------------------------------
#define ATTN_SMEM_FLOATS (8192 + 16384 + 16384 + 8192 + 192)

__global__ __launch_bounds__(256) void attn_kernel(const float* __restrict__ Q,
                                                   const float* __restrict__ K,
                                                   const float* __restrict__ V,
                                                   float* __restrict__ O)
{
    extern __shared__ float sm[];
    float* Qt  = sm;                       // 128*64
    float* Kt  = sm + 8192;                // 128*128
    float* Vs  = sm + 8192 + 16384;        // 128*128
    float* Ps  = sm + 8192 + 32768;        // 64*128
    float* m_s = sm + 49152;               // 64
    float* l_s = m_s + 64;                 // 64
    float* al_s = l_s + 64;                // 64

    const int tid = threadIdx.x;
    const int tx = tid & 15, ty = tid >> 4;
    const int bh = blockIdx.y;
    const float* Qg = Q + ((size_t)bh * LQ + blockIdx.x * 64) * Dd;
    const float* Kg = K + (size_t)bh * LKt * Dd;
    const float* Vg = V + (size_t)bh * LKt * Dd;

    // Load+transpose Q (once). Qt[k][r] at k*64 + (((r>>2)^((k>>2)&15))<<2) + (r&3)
#pragma unroll
    for (int it = 0; it < 8; ++it) {
        int f4 = tid + (it << 8);
        int r = f4 >> 5, d4 = f4 & 31;
        float4 qv = *(const float4*)&Qg[(size_t)r * Dd + (d4 << 2)];
        float v4[4] = {qv.x, qv.y, qv.z, qv.w};
#pragma unroll
        for (int jj = 0; jj < 4; ++jj) {
            int k = (d4 << 2) + jj;
            Qt[(k << 6) + ((((r >> 2) ^ (d4 & 15))) << 2) + (r & 3)] = v4[jj];
        }
    }
    if (tid < 64) { m_s[tid] = -1e30f; l_s[tid] = 0.f; }

    float o[4][8];
#pragma unroll
    for (int i = 0; i < 4; ++i)
#pragma unroll
        for (int j = 0; j < 8; ++j) o[i][j] = 0.f;

    const float scale = 0.088388347648318447f; // 1/sqrt(128)

    for (int t0 = 0; t0 < LKt; t0 += 128) {
        __syncthreads();  // prev tile's Ps/Vs consumers done; Qt/stats visible (iter 0)
        // K tile transpose: Kt[k][c] at k*128 + (((c>>2) ^ (k>>2))<<2) + (c&3)
#pragma unroll
        for (int it = 0; it < 16; ++it) {
            int f4 = tid + (it << 8);
            int c = f4 >> 5, d4 = f4 & 31;
            float4 kv = *(const float4*)&Kg[(size_t)(t0 + c) * Dd + (d4 << 2)];
            float v4[4] = {kv.x, kv.y, kv.z, kv.w};
#pragma unroll
            for (int jj = 0; jj < 4; ++jj) {
                int k = (d4 << 2) + jj;
                Kt[(k << 7) + ((((c >> 2) ^ d4)) << 2) + (c & 3)] = v4[jj];
            }
        }
        // V tile: Vs[j][c] at j*128 + (((c>>2) ^ (j&31))<<2) + (c&3)
#pragma unroll
        for (int it = 0; it < 16; ++it) {
            int f4 = tid + (it << 8);
            int j = f4 >> 5, c4 = f4 & 31;
            float4 vv = *(const float4*)&Vg[(size_t)(t0 + j) * Dd + (c4 << 2)];
            *(float4*)&Vs[(j << 7) + (((c4 ^ (j & 31))) << 2)] = vv;
        }
        __syncthreads();

        // S = scale * Q K^T : rows 4ty..4ty+3, cols 8tx..8tx+7
        float s[4][8];
#pragma unroll
        for (int i = 0; i < 4; ++i)
#pragma unroll
            for (int j = 0; j < 8; ++j) s[i][j] = 0.f;

#pragma unroll 4
        for (int k = 0; k < 128; ++k) {
            int sq = (k >> 2) & 15;
            int sk = (k >> 2) & 31;
            float4 qa = *(const float4*)&Qt[(k << 6) + ((ty ^ sq) << 2)];
            float4 b0 = *(const float4*)&Kt[(k << 7) + ((((2 * tx) ^ sk)) << 2)];
            float4 b1 = *(const float4*)&Kt[(k << 7) + ((((2 * tx + 1) ^ sk)) << 2)];
            float aa[4] = {qa.x, qa.y, qa.z, qa.w};
            float bb[8] = {b0.x, b0.y, b0.z, b0.w, b1.x, b1.y, b1.z, b1.w};
#pragma unroll
            for (int i = 0; i < 4; ++i)
#pragma unroll
                for (int j = 0; j < 8; ++j) s[i][j] += aa[i] * bb[j];
        }
        // write scores to Ps (swizzled)
#pragma unroll
        for (int i = 0; i < 4; ++i) {
            int rr = 4 * ty + i;
            float4 p0 = make_float4(s[i][0] * scale, s[i][1] * scale, s[i][2] * scale, s[i][3] * scale);
            float4 p1 = make_float4(s[i][4] * scale, s[i][5] * scale, s[i][6] * scale, s[i][7] * scale);
            *(float4*)&Ps[(rr << 7) + ((((2 * tx) ^ (rr & 31))) << 2)]     = p0;
            *(float4*)&Ps[(rr << 7) + ((((2 * tx + 1) ^ (rr & 31))) << 2)] = p1;
        }
        __syncthreads();

        // Online softmax: 4 threads per row, 32 cols each
        {
            int r = tid >> 2, qq = tid & 3;
            float mloc = -1e30f;
#pragma unroll
            for (int t = 0; t < 8; ++t) {
                int g = (qq << 3) + t;
                float4 pv = *(const float4*)&Ps[(r << 7) + (((g ^ (r & 31))) << 2)];
                mloc = fmaxf(mloc, fmaxf(fmaxf(pv.x, pv.y), fmaxf(pv.z, pv.w)));
            }
            mloc = fmaxf(mloc, __shfl_xor_sync(0xffffffffu, mloc, 1));
            mloc = fmaxf(mloc, __shfl_xor_sync(0xffffffffu, mloc, 2));
            float m_old = m_s[r];
            float m_new = fmaxf(m_old, mloc);
            float suml = 0.f;
#pragma unroll
            for (int t = 0; t < 8; ++t) {
                int g = (qq << 3) + t;
                float* pp = &Ps[(r << 7) + (((g ^ (r & 31))) << 2)];
                float4 pv = *(const float4*)pp;
                pv.x = __expf(pv.x - m_new);
                pv.y = __expf(pv.y - m_new);
                pv.z = __expf(pv.z - m_new);
                pv.w = __expf(pv.w - m_new);
                suml += pv.x + pv.y + pv.z + pv.w;
                *(float4*)pp = pv;
            }
            suml += __shfl_xor_sync(0xffffffffu, suml, 1);
            suml += __shfl_xor_sync(0xffffffffu, suml, 2);
            __syncwarp();
            if (qq == 0) {
                float a = __expf(m_old - m_new);
                al_s[r] = a;
                l_s[r] = l_s[r] * a + suml;
                m_s[r] = m_new;
            }
        }
        __syncthreads();

        // O = O*alpha + P V : rows 4ty..4ty+3, cols 8tx..8tx+7
#pragma unroll
        for (int i = 0; i < 4; ++i) {
            float a = al_s[4 * ty + i];
#pragma unroll
            for (int j = 0; j < 8; ++j) o[i][j] *= a;
        }
#pragma unroll 4
        for (int j = 0; j < 128; ++j) {
            int sv = j & 31;
            float4 v0 = *(const float4*)&Vs[(j << 7) + ((((2 * tx) ^ sv)) << 2)];
            float4 v1 = *(const float4*)&Vs[(j << 7) + ((((2 * tx + 1) ^ sv)) << 2)];
            float vv[8] = {v0.x, v0.y, v0.z, v0.w, v1.x, v1.y, v1.z, v1.w};
#pragma unroll
            for (int i = 0; i < 4; ++i) {
                int rr = 4 * ty + i;
                float p = Ps[(rr << 7) + ((((j >> 2) ^ (rr & 31))) << 2) + (j & 3)];
#pragma unroll
                for (int jc = 0; jc < 8; ++jc) o[i][jc] += p * vv[jc];
            }
        }
    }

    // Normalize + write to g_AT [b][l][h*128 + c]
    int bidx = bh >> 3, h = bh & 7;
#pragma unroll
    for (int i = 0; i < 4; ++i) {
        int rr = 4 * ty + i;
        float invl = 1.0f / l_s[rr];
        size_t base = (((size_t)bidx * LQ) + blockIdx.x * 64 + rr) * (Hh * Dd) + h * Dd + 8 * tx;
        float4 o0 = make_float4(o[i][0] * invl, o[i][1] * invl, o[i][2] * invl, o[i][3] * invl);
        float4 o1 = make_float4(o[i][4] * invl, o[i][5] * invl, o[i][6] * invl, o[i][7] * invl);
        *(float4*)&O[base]     = o0;
        *(float4*)&O[base + 4] = o1;
    }
}

// ---------------------------------------------------------------------------
extern "C" void kernel_launch(void* const* d_in, const int* in_sizes, int n_in,
                              void* d_out, int out_size)
{
    const float* q  = (const float*)d_in[0];
    const float* k  = (const float*)d_in[1];
    const float* v  = (const float*)d_in[2];
    const float* Wq = (const float*)d_in[3];
    const float* bq = (const float*)d_in[4];
    const float* Wk = (const float*)d_in[5];
    const float* bk = (const float*)d_in[6];
    const float* Wv = (const float*)d_in[7];
    const float* bv = (const float*)d_in[8];
    const float* Wo = (const float*)d_in[9];
    const float* bo = (const float*)d_in[10];
    float* out = (float*)d_out;

    float *gQ, *gK, *gV, *gA;
    cudaGetSymbolAddress((void**)&gQ, g_Q);
    cudaGetSymbolAddress((void**)&gK, g_K);
    cudaGetSymbolAddress((void**)&gV, g_V);
    cudaGetSymbolAddress((void**)&gA, g_AT);

    const int attn_smem = ATTN_SMEM_FLOATS * 4;
    cudaFuncSetAttribute(attn_kernel, cudaFuncAttributeMaxDynamicSharedMemorySize, attn_smem);

    dim3 gproj(128, 8);   // M/128=128, N/128=8
    gemm_kernel<128, 1024, true><<<gproj, 256>>>(q, Wq, bq, gQ);
    gemm_kernel<128, 1024, true><<<gproj, 256>>>(k, Wk, bk, gK);
    gemm_kernel<128, 1024, true><<<gproj, 256>>>(v, Wv, bv, gV);

    attn_kernel<<<dim3(LQ / 64, Bb * Hh), 256, attn_smem>>>(gQ, gK, gV, gA);

    gemm_kernel<1024, 128, false><<<dim3(128, 1), 256>>>(gA, Wo, bo, out);
}

// round 3
// speedup vs baseline: 4.5837x; 4.5837x over previous
#include <cuda_runtime.h>
#include <cstdint>
#include <cstddef>

// Problem shapes (fixed)
#define Bb  8
#define LQn 2048
#define LKn 2048
#define Dd  128
#define Hh  8

// Scratch (head-major Q/K/V, tf32-rounded; attention output row-major [b][l][h*d])
__device__ float g_Q[(size_t)Bb * Hh * LQn * Dd];
__device__ float g_K[(size_t)Bb * Hh * LKn * Dd];
__device__ float g_V[(size_t)Bb * Hh * LKn * Dd];
__device__ float g_AT[(size_t)Bb * LQn * Hh * Dd];

// ---------------------------------------------------------------------------
// Helpers
// ---------------------------------------------------------------------------
__device__ __forceinline__ float tf32r(float x) {
    uint32_t r; asm("cvt.rna.tf32.f32 %0, %1;" : "=r"(r) : "f"(x));
    return __uint_as_float(r);
}
__device__ __forceinline__ float ex2f(float x) {
    float y; asm("ex2.approx.ftz.f32 %0, %1;" : "=f"(y) : "f"(x));
    return y;
}
// D += A * B   (m16n8k8, tf32, A row-major, B col-major)
__device__ __forceinline__ void mma8(float d[4], const uint32_t a[4],
                                     uint32_t b0, uint32_t b1) {
    asm volatile(
        "mma.sync.aligned.m16n8k8.row.col.f32.tf32.tf32.f32 "
        "{%0,%1,%2,%3},{%4,%5,%6,%7},{%8,%9},{%0,%1,%2,%3};"
        : "+f"(d[0]), "+f"(d[1]), "+f"(d[2]), "+f"(d[3])
        : "r"(a[0]), "r"(a[1]), "r"(a[2]), "r"(a[3]), "r"(b0), "r"(b1));
}
// Swizzle: col' = col ^ SWZ(row). Conflict-free for both (col=t,row=g) and
// (col=g,row=t) fragment access patterns; bit2-aligned so float4 stores stay contiguous.
#define SWZ(r) ((((r) & 3) << 3) ^ ((r) & 4))

// ---------------------------------------------------------------------------
// TF32 GEMM: C[M x NW-slice] = A[M x KTOT] * Bw[KTOT x NW] + bias
// CTA tile 128x128, 8 warps, warp = m16 x n128. K-chunks of 32.
// SCATTER=true: write head-major [b][h][l][d], outputs rounded to tf32.
// ---------------------------------------------------------------------------
template <int KTOT, int NW, bool SCATTER>
__global__ __launch_bounds__(256) void gemm_tf32(const float* __restrict__ A,
                                                 const float* __restrict__ Bw,
                                                 const float* __restrict__ bias,
                                                 float* __restrict__ C)
{
    __shared__ float As[128 * 32];
    __shared__ float Bs[32 * 128];

    const int tid = threadIdx.x;
    const int lane = tid & 31, w = tid >> 5;
    const int g = lane >> 2, t = lane & 3;
    const int m0 = blockIdx.x * 128, n0 = blockIdx.y * 128;
    const int swg = SWZ(g);
    const int swb0 = t << 3, swb1 = (t << 3) ^ 4;

    float acc[16][4];
#pragma unroll
    for (int j = 0; j < 16; ++j)
#pragma unroll
        for (int i = 0; i < 4; ++i) acc[j][i] = 0.f;

    for (int kc = 0; kc < KTOT; kc += 32) {
        __syncthreads();
        // Stage A: 128 rows x 32 k (tf32-rounded, swizzled)
#pragma unroll
        for (int it = 0; it < 4; ++it) {
            int f = tid + (it << 8);
            int r = f >> 3, k4 = (f & 7) << 2;
            float4 v = *(const float4*)&A[(size_t)(m0 + r) * KTOT + kc + k4];
            float4 o = make_float4(tf32r(v.x), tf32r(v.y), tf32r(v.z), tf32r(v.w));
            *(float4*)&As[r * 32 + (k4 ^ SWZ(r))] = o;
        }
        // Stage B: 32 k x 128 n (tf32-rounded, swizzled)
#pragma unroll
        for (int it = 0; it < 4; ++it) {
            int f = tid + (it << 8);
            int k = f >> 5, n4 = (f & 31) << 2;
            float4 v = *(const float4*)&Bw[(size_t)(kc + k) * NW + n0 + n4];
            float4 o = make_float4(tf32r(v.x), tf32r(v.y), tf32r(v.z), tf32r(v.w));
            *(float4*)&Bs[k * 128 + (n4 ^ SWZ(k))] = o;
        }
        __syncthreads();

#pragma unroll
        for (int kk = 0; kk < 4; ++kk) {
            uint32_t a[4];
            a[0] = __float_as_uint(As[(16 * w + g) * 32 + ((8 * kk + t) ^ swg)]);
            a[1] = __float_as_uint(As[(16 * w + g + 8) * 32 + ((8 * kk + t) ^ swg)]);
            a[2] = __float_as_uint(As[(16 * w + g) * 32 + ((8 * kk + t + 4) ^ swg)]);
            a[3] = __float_as_uint(As[(16 * w + g + 8) * 32 + ((8 * kk + t + 4) ^ swg)]);
#pragma unroll
            for (int jn = 0; jn < 16; ++jn) {
                uint32_t b0 = __float_as_uint(Bs[(8 * kk + t) * 128 + ((8 * jn + g) ^ swb0)]);
                uint32_t b1 = __float_as_uint(Bs[(8 * kk + t + 4) * 128 + ((8 * jn + g) ^ swb1)]);
                mma8(acc[jn], a, b0, b1);
            }
        }
    }

    // Epilogue: rows m0+16w+g and +8; cols n0+8jn+2t, +1
    const int r0 = m0 + 16 * w + g;
    const int r1 = r0 + 8;
#pragma unroll
    for (int jn = 0; jn < 16; ++jn) {
        int col = n0 + 8 * jn + 2 * t;
        float b0v = bias[col], b1v = bias[col + 1];
        float v00 = acc[jn][0] + b0v, v01 = acc[jn][1] + b1v;
        float v10 = acc[jn][2] + b0v, v11 = acc[jn][3] + b1v;
        if (SCATTER) {
            // n-block == one head (128 cols): h = blockIdx.y, d = col - n0
            int d = 8 * jn + 2 * t;
            int b0i = r0 >> 11, l0i = r0 & 2047;
            int b1i = r1 >> 11, l1i = r1 & 2047;
            size_t base0 = (((size_t)b0i * Hh + blockIdx.y) * LQn + l0i) * Dd + d;
            size_t base1 = (((size_t)b1i * Hh + blockIdx.y) * LQn + l1i) * Dd + d;
            float2 p0 = make_float2(tf32r(v00), tf32r(v01));
            float2 p1 = make_float2(tf32r(v10), tf32r(v11));
            *(float2*)&C[base0] = p0;
            *(float2*)&C[base1] = p1;
        } else {
            *(float2*)&C[(size_t)r0 * NW + col] = make_float2(v00, v01);
            *(float2*)&C[(size_t)r1 * NW + col] = make_float2(v10, v11);
        }
    }
}

// ---------------------------------------------------------------------------
// Flash attention, TF32 tensor cores.
// CTA = 128 q-rows of one (b,h). 8 warps, warp = m16 rows x full 64-col K-tile.
// K/V tiles token-major [64][128] in smem, SWZ-swizzled (conflict-free for
// both S-phase and O-phase fragment loads). Q A-fragments in registers.
// ---------------------------------------------------------------------------
__global__ __launch_bounds__(256) void attn_tf32(const float* __restrict__ Q,
                                                 const float* __restrict__ K,
                                                 const float* __restrict__ V,
                                                 float* __restrict__ O)
{
    extern __shared__ float sm[];
    float* Ks = sm;             // 64 x 128
    float* Vs = sm + 64 * 128;  // 64 x 128

    const int tid = threadIdx.x;
    const int lane = tid & 31, w = tid >> 5;
    const int g = lane >> 2, t = lane & 3;
    const int swg = SWZ(g);
    const int swt0 = t << 3, swt1 = (t << 3) ^ 4;

    const int bh = blockIdx.y;
    const int q0 = blockIdx.x * 128;
    const float* Qg = Q + ((size_t)bh * LQn + q0) * Dd;
    const float* Kg = K + (size_t)bh * LKn * Dd;
    const float* Vg = V + (size_t)bh * LKn * Dd;

    // Q A-fragments (already tf32-rounded in scratch): rows 16w+g, 16w+g+8
    const int qr0 = 16 * w + g, qr1 = qr0 + 8;
    uint32_t qa[16][4];
#pragma unroll
    for (int kk = 0; kk < 16; ++kk) {
        qa[kk][0] = __float_as_uint(Qg[(size_t)qr0 * Dd + 8 * kk + t]);
        qa[kk][1] = __float_as_uint(Qg[(size_t)qr1 * Dd + 8 * kk + t]);
        qa[kk][2] = __float_as_uint(Qg[(size_t)qr0 * Dd + 8 * kk + t + 4]);
        qa[kk][3] = __float_as_uint(Qg[(size_t)qr1 * Dd + 8 * kk + t + 4]);
    }

    float of[16][4];
#pragma unroll
    for (int j = 0; j < 16; ++j)
#pragma unroll
        for (int i = 0; i < 4; ++i) of[j][i] = 0.f;

    float m0r = -1e30f, m1r = -1e30f, l0 = 0.f, l1 = 0.f;
    const float Cs = 0.12751539f;  // (1/sqrt(128)) * log2(e)

    for (int t0 = 0; t0 < LKn; t0 += 64) {
        __syncthreads();
        // Stage K, V tiles (token-major, swizzled; data pre-rounded to tf32)
#pragma unroll
        for (int it = 0; it < 8; ++it) {
            int f = tid + (it << 8);
            int tok = f >> 5, d4 = (f & 31) << 2;
            int dst = tok * 128 + (d4 ^ SWZ(tok));
            *(float4*)&Ks[dst] = *(const float4*)&Kg[(size_t)(t0 + tok) * Dd + d4];
            *(float4*)&Vs[dst] = *(const float4*)&Vg[(size_t)(t0 + tok) * Dd + d4];
        }
        __syncthreads();

        // ---- S = Q K^T  (m16 x n64 per warp) ----
        float sf[8][4];
#pragma unroll
        for (int j = 0; j < 8; ++j)
#pragma unroll
            for (int i = 0; i < 4; ++i) sf[j][i] = 0.f;

#pragma unroll
        for (int kk = 0; kk < 16; ++kk) {
#pragma unroll
            for (int j = 0; j < 8; ++j) {
                uint32_t b0 = __float_as_uint(Ks[(8 * j + g) * 128 + ((8 * kk + t) ^ swg)]);
                uint32_t b1 = __float_as_uint(Ks[(8 * j + g) * 128 + ((8 * kk + t + 4) ^ swg)]);
                mma8(sf[j], qa[kk], b0, b1);
            }
        }

        // ---- online softmax (registers + quad shuffles) ----
        float mx0 = -1e30f, mx1 = -1e30f;
#pragma unroll
        for (int j = 0; j < 8; ++j) {
            mx0 = fmaxf(mx0, fmaxf(sf[j][0], sf[j][1]));
            mx1 = fmaxf(mx1, fmaxf(sf[j][2], sf[j][3]));
        }
        mx0 = fmaxf(mx0, __shfl_xor_sync(0xffffffffu, mx0, 1));
        mx0 = fmaxf(mx0, __shfl_xor_sync(0xffffffffu, mx0, 2));
        mx1 = fmaxf(mx1, __shfl_xor_sync(0xffffffffu, mx1, 1));
        mx1 = fmaxf(mx1, __shfl_xor_sync(0xffffffffu, mx1, 2));
        float mn0 = fmaxf(m0r, mx0), mn1 = fmaxf(m1r, mx1);
        float al0 = ex2f((m0r - mn0) * Cs), al1 = ex2f((m1r - mn1) * Cs);
        m0r = mn0; m1r = mn1;

        float s0 = 0.f, s1 = 0.f;
#pragma unroll
        for (int j = 0; j < 8; ++j) {
            sf[j][0] = ex2f((sf[j][0] - mn0) * Cs);
            sf[j][1] = ex2f((sf[j][1] - mn0) * Cs);
            sf[j][2] = ex2f((sf[j][2] - mn1) * Cs);
            sf[j][3] = ex2f((sf[j][3] - mn1) * Cs);
            s0 += sf[j][0] + sf[j][1];
            s1 += sf[j][2] + sf[j][3];
        }
        s0 += __shfl_xor_sync(0xffffffffu, s0, 1);
        s0 += __shfl_xor_sync(0xffffffffu, s0, 2);
        s1 += __shfl_xor_sync(0xffffffffu, s1, 1);
        s1 += __shfl_xor_sync(0xffffffffu, s1, 2);
        l0 = l0 * al0 + s0;
        l1 = l1 * al1 + s1;

#pragma unroll
        for (int jn = 0; jn < 16; ++jn) {
            of[jn][0] *= al0; of[jn][1] *= al0;
            of[jn][2] *= al1; of[jn][3] *= al1;
        }

        // ---- O += P V  (P: C-frag -> A-frag via quad shuffles) ----
        const int qbase = lane & 28;
        const int srcA = qbase + (t >> 1), srcB = srcA + 2;
        const bool odd = (t & 1);
#pragma unroll
        for (int j = 0; j < 8; ++j) {  // k-tile over tokens
            float v0 = __shfl_sync(0xffffffffu, sf[j][0], srcA);
            float v1 = __shfl_sync(0xffffffffu, sf[j][1], srcA);
            float v2 = __shfl_sync(0xffffffffu, sf[j][2], srcA);
            float v3 = __shfl_sync(0xffffffffu, sf[j][3], srcA);
            float w0 = __shfl_sync(0xffffffffu, sf[j][0], srcB);
            float w1 = __shfl_sync(0xffffffffu, sf[j][1], srcB);
            float w2 = __shfl_sync(0xffffffffu, sf[j][2], srcB);
            float w3 = __shfl_sync(0xffffffffu, sf[j][3], srcB);
            uint32_t a[4];
            a[0] = __float_as_uint(tf32r(odd ? v1 : v0));
            a[1] = __float_as_uint(tf32r(odd ? v3 : v2));
            a[2] = __float_as_uint(tf32r(odd ? w1 : w0));
            a[3] = __float_as_uint(tf32r(odd ? w3 : w2));
#pragma unroll
            for (int jn = 0; jn < 16; ++jn) {
                uint32_t b0 = __float_as_uint(Vs[(8 * j + t) * 128 + ((8 * jn + g) ^ swt0)]);
                uint32_t b1 = __float_as_uint(Vs[(8 * j + t + 4) * 128 + ((8 * jn + g) ^ swt1)]);
                mma8(of[jn], a, b0, b1);
            }
        }
    }

    // Epilogue: normalize, round to tf32 (consumed by out-proj), write [b][l][h*d]
    const float i0 = 1.f / l0, i1 = 1.f / l1;
    const int bidx = bh >> 3, h = bh & 7;
    const size_t row0 = ((size_t)bidx * LQn + q0 + qr0) * (Hh * Dd) + (size_t)h * Dd;
    const size_t row1 = row0 + (size_t)8 * (Hh * Dd);
#pragma unroll
    for (int jn = 0; jn < 16; ++jn) {
        int col = 8 * jn + 2 * t;
        float2 p0 = make_float2(tf32r(of[jn][0] * i0), tf32r(of[jn][1] * i0));
        float2 p1 = make_float2(tf32r(of[jn][2] * i1), tf32r(of[jn][3] * i1));
        *(float2*)&O[row0 + col] = p0;
        *(float2*)&O[row1 + col] = p1;
    }
}

// ---------------------------------------------------------------------------
extern "C" void kernel_launch(void* const* d_in, const int* in_sizes, int n_in,
                              void* d_out, int out_size)
{
    const float* q  = (const float*)d_in[0];
    const float* k  = (const float*)d_in[1];
    const float* v  = (const float*)d_in[2];
    const float* Wq = (const float*)d_in[3];
    const float* bq = (const float*)d_in[4];
    const float* Wk = (const float*)d_in[5];
    const float* bk = (const float*)d_in[6];
    const float* Wv = (const float*)d_in[7];
    const float* bv = (const float*)d_in[8];
    const float* Wo = (const float*)d_in[9];
    const float* bo = (const float*)d_in[10];
    float* out = (float*)d_out;

    float *gQ, *gK, *gV, *gA;
    cudaGetSymbolAddress((void**)&gQ, g_Q);
    cudaGetSymbolAddress((void**)&gK, g_K);
    cudaGetSymbolAddress((void**)&gV, g_V);
    cudaGetSymbolAddress((void**)&gA, g_AT);

    const int attn_smem = 2 * 64 * 128 * 4;  // 64 KB
    cudaFuncSetAttribute(attn_tf32, cudaFuncAttributeMaxDynamicSharedMemorySize, attn_smem);

    dim3 gproj(128, 8);  // 16384/128 x 1024/128
    gemm_tf32<128, 1024, true><<<gproj, 256>>>(q, Wq, bq, gQ);
    gemm_tf32<128, 1024, true><<<gproj, 256>>>(k, Wk, bk, gK);
    gemm_tf32<128, 1024, true><<<gproj, 256>>>(v, Wv, bv, gV);

    attn_tf32<<<dim3(LQn / 128, Bb * Hh), 256, attn_smem>>>(gQ, gK, gV, gA);

    gemm_tf32<1024, 128, false><<<dim3(128, 1), 256>>>(gA, Wo, bo, out);
}